// round 15
// baseline (speedup 1.0000x reference)
#include <cuda_runtime.h>
#include <cuda_bf16.h>
#include <cuda_fp16.h>
#include <math.h>
#include <stdint.h>

#define BB 2
#define LL 2048
#define DD 1024
#define HH 16
#define HDIM 64
#define D3 3072
#define RLEN 4095   // 2*L - 1
#define MTOT 4096   // B*L
#define K2 2048     // hi|lo concatenated K

// Scratch (no allocation allowed)
__device__ float g_scores[HH * RLEN];
__device__ __align__(1024) __half g_Abig[(size_t)MTOT * K2];  // x  fp16 hi|lo
__device__ __align__(1024) __half g_Bbig[(size_t)D3 * K2];    // w  fp16 hi|lo(unused)
// Per-head fp16 tensors: [b][h][l][64]. Q exact (hi+lo); K,V single fp16.
#define HSZ ((size_t)BB * HH * LL * HDIM)
__device__ __align__(1024) __half g_Qh[HSZ];
__device__ __align__(1024) __half g_Ql[HSZ];
__device__ __align__(1024) __half g_Kh[HSZ];
__device__ __align__(1024) __half g_Vh[HSZ];
__device__ __align__(1024) __half g_Dump[HSZ];  // lo-half sink for K/V (unused data)

__device__ __forceinline__ uint32_t smem_to_u32(const void* p) {
    uint32_t a;
    asm("{ .reg .u64 t; cvta.to.shared.u64 t, %1; cvt.u32.u64 %0, t; }"
        : "=r"(a) : "l"(p));
    return a;
}
#define CP16(dst, src) \
    asm volatile("cp.async.cg.shared.global [%0], [%1], 16;" :: "r"(dst), "l"(src))
#define CP_COMMIT() asm volatile("cp.async.commit_group;" ::: "memory")
#define CP_WAITG(n) asm volatile("cp.async.wait_group %0;" :: "n"(n) : "memory")

__device__ __forceinline__ void ldsm4(uint32_t* r, uint32_t addr) {
    asm volatile("ldmatrix.sync.aligned.m8n8.x4.shared.b16 {%0, %1, %2, %3}, [%4];"
                 : "=r"(r[0]), "=r"(r[1]), "=r"(r[2]), "=r"(r[3]) : "r"(addr));
}
__device__ __forceinline__ void ldsm4t(uint32_t* r, uint32_t addr) {
    asm volatile("ldmatrix.sync.aligned.m8n8.x4.trans.shared.b16 {%0, %1, %2, %3}, [%4];"
                 : "=r"(r[0]), "=r"(r[1]), "=r"(r[2]), "=r"(r[3]) : "r"(addr));
}
__device__ __forceinline__ void mma16816h(float* c, const uint32_t* a, const uint32_t* b) {
    asm volatile("mma.sync.aligned.m16n8k16.row.col.f32.f16.f16.f32 "
                 "{%0, %1, %2, %3}, {%4, %5, %6, %7}, {%8, %9}, {%0, %1, %2, %3};"
                 : "+f"(c[0]), "+f"(c[1]), "+f"(c[2]), "+f"(c[3])
                 : "r"(a[0]), "r"(a[1]), "r"(a[2]), "r"(a[3]), "r"(b[0]), "r"(b[1]));
}
// packed f16x2: low half = lo, high half = hi
__device__ __forceinline__ uint32_t packhf(float lo, float hi) {
    uint32_t r;
    asm("cvt.rn.f16x2.f32 %0, %1, %2;" : "=r"(r) : "f"(hi), "f"(lo));
    return r;
}
__device__ __forceinline__ float lowh(uint32_t p) {
    return __half2float(__ushort_as_half((unsigned short)(p & 0xFFFFu)));
}
__device__ __forceinline__ float highh(uint32_t p) {
    return __half2float(__ushort_as_half((unsigned short)(p >> 16)));
}

// ---------------------------------------------------------------------------
// Kernel 1: fused fp32 -> fp16 hi/lo split for x and w_in + TISA bias table
// as 128 tail blocks (one launch).
// ---------------------------------------------------------------------------
__global__ __launch_bounds__(256) void convert2_kernel(const float* __restrict__ x,
                                                       const float* __restrict__ w,
                                                       const float* __restrict__ off,
                                                       const float* __restrict__ amp,
                                                       const float* __restrict__ shp)
{
    __shared__ float so[16], sa[16], ss[16];
    int blk = blockIdx.x;
    if (blk >= MTOT + D3) {
        int b2 = blk - (MTOT + D3);
        int h = b2 >> 3, slice = b2 & 7;
        if (threadIdx.x < 16) {
            so[threadIdx.x] = off[h * 16 + threadIdx.x];
            sa[threadIdx.x] = amp[h * 16 + threadIdx.x];
            ss[threadIdx.x] = fabsf(shp[h * 16 + threadIdx.x]);
        }
        __syncthreads();
        for (int r = slice * 256 + threadIdx.x; r < RLEN; r += 8 * 256) {
            float rel = (float)(r - (LL - 1));
            float acc = 0.f;
#pragma unroll
            for (int k = 0; k < 16; k++) {
                float d = so[k] - rel;
                acc += sa[k] * expf(-ss[k] * d * d);
            }
            g_scores[h * RLEN + r] = acc;
        }
        return;
    }

    int idx = blk * 256 + threadIdx.x;
    int row = idx >> 8;
    int k = (idx & 255) << 2;
    const float* src;
    __half* dst;
    int r;
    if (row < MTOT) { src = x; dst = g_Abig; r = row; }
    else            { src = w; dst = g_Bbig; r = row - MTOT; }
    float4 v = *(const float4*)(src + (size_t)r * DD + k);
    float h0 = __half2float(__float2half_rn(v.x));
    float h1 = __half2float(__float2half_rn(v.y));
    float h2 = __half2float(__float2half_rn(v.z));
    float h3 = __half2float(__float2half_rn(v.w));
    uint32_t ph01 = packhf(h0, h1);
    uint32_t ph23 = packhf(h2, h3);
    uint32_t pl01 = packhf(v.x - h0, v.y - h1);
    uint32_t pl23 = packhf(v.z - h2, v.w - h3);
    uint32_t* dh = (uint32_t*)(dst + (size_t)r * K2 + k);
    dh[0] = ph01;
    dh[1] = ph23;
    uint32_t* dl = (uint32_t*)(dst + (size_t)r * K2 + DD + k);
    dl[0] = pl01;
    dl[1] = pl23;
}

// ---------------------------------------------------------------------------
// Kernel 2: fp16 HMMA 2-pass GEMM — R7/R11 loop structure (both barriers
// load-bearing; mainloop body unchanged except f16 opcode + kamap).
// 32 chunks: 16x Ahi*Bh, 16x Alo*Bh. fp32 accum. 2 CTAs/SM.
// ---------------------------------------------------------------------------
#define NCHUNK 32
#define STG_BYTES 32768

__device__ __forceinline__ void load_chunk(uint32_t sA, uint32_t sB,
                                           const __half* __restrict__ gA,
                                           const __half* __restrict__ gB,
                                           int bm, int bn, int ka, int kb, int tid)
{
#pragma unroll
    for (int i = 0; i < 4; i++) {
        int s = tid + i * 256;
        int row = s >> 3, kseg = s & 7;
        uint32_t dst = sA + row * 128 + ((kseg ^ (row & 7)) << 4);
        const void* src = gA + (size_t)(bm + row) * K2 + ka + kseg * 8;
        CP16(dst, src);
    }
#pragma unroll
    for (int i = 0; i < 4; i++) {
        int s = tid + i * 256;
        int row = s >> 3, kseg = s & 7;
        uint32_t dst = sB + row * 128 + ((kseg ^ (row & 7)) << 4);
        const void* src = gB + (size_t)(bn + row) * K2 + kb + kseg * 8;
        CP16(dst, src);
    }
    CP_COMMIT();
}

__global__ __launch_bounds__(256, 2) void proj_mma()
{
    extern __shared__ char smem[];
    const uint32_t sbase = smem_to_u32(smem);
    const int tid = threadIdx.x;
    const int wid = tid >> 5, lane = tid & 31;
    const int bm = blockIdx.y * 128, bn = blockIdx.x * 128;
    const int wm = (wid >> 1) * 32;
    const int wn = (wid & 1) * 64;

    float acc[2][8][4];
#pragma unroll
    for (int mt = 0; mt < 2; mt++)
#pragma unroll
        for (int nt = 0; nt < 8; nt++)
#pragma unroll
            for (int c = 0; c < 4; c++) acc[mt][nt][c] = 0.f;

    // chunk t: pass 0 (t<16): Ahi*Bh; pass 1 (t>=16): Alo*Bh
    auto kamap = [](int t, int& ka, int& kb) {
        int pass = t >> 4, kt = t & 15;
        ka = pass ? (DD + kt * 64) : (kt * 64);
        kb = kt * 64;
    };

    {
        int ka, kb;
        kamap(0, ka, kb);
        load_chunk(sbase, sbase + 16384, g_Abig, g_Bbig, bm, bn, ka, kb, tid);
        kamap(1, ka, kb);
        load_chunk(sbase + STG_BYTES, sbase + STG_BYTES + 16384, g_Abig, g_Bbig,
                   bm, bn, ka, kb, tid);
    }

    for (int t = 0; t < NCHUNK; t++) {
        CP_WAITG(1);
        __syncthreads();

        if (t + 2 < NCHUNK) {
            int ka, kb;
            kamap(t + 2, ka, kb);
            uint32_t s = sbase + ((t + 2) % 3) * STG_BYTES;
            load_chunk(s, s + 16384, g_Abig, g_Bbig, bm, bn, ka, kb, tid);
        } else {
            CP_COMMIT();
        }

        const uint32_t sA = sbase + (t % 3) * STG_BYTES;
        const uint32_t sB = sA + 16384;

#pragma unroll
        for (int kk = 0; kk < 4; kk++) {
            uint32_t a[2][4];
#pragma unroll
            for (int mt = 0; mt < 2; mt++) {
                int row = wm + mt * 16 + (lane & 15);
                int kseg = kk * 2 + (lane >> 4);
                uint32_t addr = sA + row * 128 + ((kseg ^ (row & 7)) << 4);
                ldsm4(a[mt], addr);
            }
            uint32_t b[8][2];
#pragma unroll
            for (int p = 0; p < 4; p++) {
                int row = wn + p * 16 + (lane & 7) + ((lane >> 4) << 3);
                int kseg = kk * 2 + ((lane >> 3) & 1);
                uint32_t addr = sB + row * 128 + ((kseg ^ (row & 7)) << 4);
                ldsm4(&b[2 * p][0], addr);
            }
#pragma unroll
            for (int mt = 0; mt < 2; mt++)
#pragma unroll
                for (int nt = 0; nt < 8; nt++)
                    mma16816h(acc[mt][nt], a[mt], b[nt]);
        }
        __syncthreads();   // load-bearing: fences ptxas pipelining (reg cap)
    }

    // Epilogue (uniform path, R13-proven shape): fp16 hi/lo packs + ptr select.
#pragma unroll
    for (int mt = 0; mt < 2; mt++) {
        int row0 = bm + wm + mt * 16 + (lane >> 2);
        int b = row0 >> 11;
        int l = row0 & 2047;
#pragma unroll
        for (int nt = 0; nt < 8; nt++) {
            int col = bn + wn + nt * 8 + (lane & 3) * 2;
            int ty = col >> 10;            // 0=k, 1=v, 2=q
            int h = (col >> 6) & 15;
            int d = col & 63;
            float sc = (ty == 2) ? 0.125f : 1.0f;
            float v0 = acc[mt][nt][0] * sc, v1 = acc[mt][nt][1] * sc;
            float v2 = acc[mt][nt][2] * sc, v3 = acc[mt][nt][3] * sc;
            uint32_t h01 = packhf(v0, v1), h23 = packhf(v2, v3);
            uint32_t l01 = packhf(v0 - lowh(h01), v1 - highh(h01));
            uint32_t l23 = packhf(v2 - lowh(h23), v3 - highh(h23));
            __half *dh, *dl;
            if (ty == 0)      { dh = g_Kh; dl = g_Dump; }
            else if (ty == 1) { dh = g_Vh; dl = g_Dump; }
            else              { dh = g_Qh; dl = g_Ql; }
            size_t base0 = ((size_t)(b * HH + h) * LL + l) * HDIM + d;
            size_t base1 = base0 + 8 * HDIM;
            *(uint32_t*)(dh + base0) = h01;
            *(uint32_t*)(dl + base0) = l01;
            *(uint32_t*)(dh + base1) = h23;
            *(uint32_t*)(dl + base1) = l23;
        }
    }
}

// ---------------------------------------------------------------------------
// Kernel 3: fp16 HMMA flash attention, 2 CTAs/SM. (R12/R13, unchanged.)
// QK 2-pass: (Qhi+Qlo)*Kh. PV 2-pass: (Phi+Plo)*Vh, P split in registers.
// smem: KV stage s at s*16384 (Kh 8KB | Vh 8KB);
//       Q @32768 (hi 16KB, lo 16KB); bias sb[2][192] @65536.
// ---------------------------------------------------------------------------
#define ASTG 16384

__device__ __forceinline__ void attn_load_k(uint32_t sbase, int stage, int bh,
                                            int kb, int tid)
{
    uint32_t stg = sbase + stage * ASTG;
#pragma unroll
    for (int i = 0; i < 2; i++) {
        int s = tid + i * 256;
        int row = s >> 3, kseg = s & 7;
        uint32_t dst = stg + row * 128 + ((kseg ^ (row & 7)) << 4);
        const void* src = g_Kh + ((size_t)bh * LL + kb + row) * HDIM + kseg * 8;
        CP16(dst, src);
    }
    CP_COMMIT();
}
__device__ __forceinline__ void attn_load_v(uint32_t sbase, int stage, int bh,
                                            int kb, int tid)
{
    uint32_t stg = sbase + stage * ASTG + 8192;
#pragma unroll
    for (int i = 0; i < 2; i++) {
        int s = tid + i * 256;
        int row = s >> 3, kseg = s & 7;
        uint32_t dst = stg + row * 128 + ((kseg ^ (row & 7)) << 4);
        const void* src = g_Vh + ((size_t)bh * LL + kb + row) * HDIM + kseg * 8;
        CP16(dst, src);
    }
    CP_COMMIT();
}

__global__ __launch_bounds__(256, 2) void attn_mma(float* __restrict__ out)
{
    extern __shared__ char smem[];
    const uint32_t sbase = smem_to_u32(smem);
    const uint32_t sQ = sbase + 32768;     // Q hi @ +0, Q lo @ +16384
    float* sb = (float*)(smem + 65536);    // [2][192]
    const int tid = threadIdx.x;
    const int wid = tid >> 5, lane = tid & 31;
    const int gid = lane >> 2, tg = lane & 3;
    const int qb = blockIdx.x * 128;
    const int h = blockIdx.y, b = blockIdx.z;
    const int bh = b * HH + h;
    const int wm = wid * 16;
    const float* srow = g_scores + h * RLEN;

    // --- Prologue: Q (hi/lo) into dedicated smem; K0/V0 issued right behind.
#pragma unroll
    for (int i = 0; i < 8; i++) {
        const int comp = i >> 2;
        int s = tid + (i & 3) * 256;
        int row = s >> 3, kseg = s & 7;
        const __half* gb = comp ? g_Ql : g_Qh;
        uint32_t dst = sQ + comp * 16384 + row * 128 + ((kseg ^ (row & 7)) << 4);
        const void* src = gb + ((size_t)bh * LL + qb + row) * HDIM + kseg * 8;
        CP16(dst, src);
    }
    CP_COMMIT();                         // group: Q
    attn_load_k(sbase, 0, bh, 0, tid);   // group: K0
    attn_load_v(sbase, 0, bh, 0, tid);   // group: V0
    if (tid < 192) {
        int sidx = qb + 1984 + tid;
        sb[tid] = srow[min(sidx, RLEN - 1)];
    }
    CP_WAITG(2);                         // Q done (K0/V0 may be pending)
    __syncthreads();

    uint32_t aQh[4][4];
#pragma unroll
    for (int ks = 0; ks < 4; ks++) {
        int row = wm + (lane & 15);
        int kseg = ks * 2 + (lane >> 4);
        ldsm4(aQh[ks], sQ + row * 128 + ((kseg ^ (row & 7)) << 4));
    }

    float O[8][4];
#pragma unroll
    for (int nt = 0; nt < 8; nt++)
#pragma unroll
        for (int c = 0; c < 4; c++) O[nt][c] = 0.f;
    float m0 = -1e30f, m1 = -1e30f, l0 = 0.f, l1 = 0.f;

    for (int t = 0; t < LL / 64; t++) {
        // pending here: K(t), V(t). Wait K only.
        CP_WAITG(1);
        __syncthreads();
        const uint32_t stg = sbase + (t & 1) * ASTG;
        const float* sbt = sb + (t & 1) * 192;

        if (t + 1 < LL / 64) {
            attn_load_k(sbase, (t + 1) & 1, bh, (t + 1) * 64, tid);
            attn_load_v(sbase, (t + 1) & 1, bh, (t + 1) * 64, tid);
            if (tid < 192) {
                int sidx = qb - (t + 1) * 64 + 1984 + tid;
                sb[((t + 1) & 1) * 192 + tid] = srow[min(sidx, RLEN - 1)];
            }
        } else {
            CP_COMMIT();
            CP_COMMIT();
        }

        // ---- S = Q K^T (2-pass: Qhi*Kh + Qlo*Kh), fp32 accum
        float S[8][4];
#pragma unroll
        for (int nt = 0; nt < 8; nt++)
#pragma unroll
            for (int c = 0; c < 4; c++) S[nt][c] = 0.f;

#pragma unroll
        for (int kk = 0; kk < 4; kk++) {
            uint32_t aQl[4];
            {
                int row = wm + (lane & 15);
                int kseg = kk * 2 + (lane >> 4);
                ldsm4(aQl, sQ + 16384 + row * 128 + ((kseg ^ (row & 7)) << 4));
            }
            uint32_t kf[8][2];
            int krow = (lane & 7) + ((lane >> 4) << 3);
            int kkseg = kk * 2 + ((lane >> 3) & 1);
#pragma unroll
            for (int p = 0; p < 4; p++) {
                int row = krow + p * 16;
                uint32_t addr = stg + row * 128 + ((kkseg ^ (row & 7)) << 4);
                ldsm4(&kf[2 * p][0], addr);
            }
#pragma unroll
            for (int nt = 0; nt < 8; nt++) {
                mma16816h(S[nt], aQh[kk], kf[nt]);
                mma16816h(S[nt], aQl, kf[nt]);
            }
        }

        // ---- bias + online softmax (V load still in flight underneath)
        const int jbase = wm + gid + 63 - 2 * tg;
        float mx0 = -1e30f, mx1 = -1e30f;
#pragma unroll
        for (int nt = 0; nt < 8; nt++) {
            int j = jbase - 8 * nt;
            S[nt][0] += sbt[j];
            S[nt][1] += sbt[j - 1];
            S[nt][2] += sbt[j + 8];
            S[nt][3] += sbt[j + 7];
            mx0 = fmaxf(mx0, fmaxf(S[nt][0], S[nt][1]));
            mx1 = fmaxf(mx1, fmaxf(S[nt][2], S[nt][3]));
        }
        mx0 = fmaxf(mx0, __shfl_xor_sync(0xffffffffu, mx0, 1));
        mx0 = fmaxf(mx0, __shfl_xor_sync(0xffffffffu, mx0, 2));
        mx1 = fmaxf(mx1, __shfl_xor_sync(0xffffffffu, mx1, 1));
        mx1 = fmaxf(mx1, __shfl_xor_sync(0xffffffffu, mx1, 2));
        float nm0 = fmaxf(m0, mx0), nm1 = fmaxf(m1, mx1);
        float c0 = __expf(m0 - nm0), c1 = __expf(m1 - nm1);
        m0 = nm0; m1 = nm1;

        float rs0 = 0.f, rs1 = 0.f;
        uint32_t aPh[4][4], aPl[4][4];
#pragma unroll
        for (int nt = 0; nt < 8; nt++) {
            float p0 = __expf(S[nt][0] - nm0);
            float p1 = __expf(S[nt][1] - nm0);
            float p2 = __expf(S[nt][2] - nm1);
            float p3 = __expf(S[nt][3] - nm1);
            rs0 += p0 + p1;
            rs1 += p2 + p3;
            uint32_t h01 = packhf(p0, p1), h23 = packhf(p2, p3);
            uint32_t l01 = packhf(p0 - lowh(h01), p1 - highh(h01));
            uint32_t l23 = packhf(p2 - lowh(h23), p3 - highh(h23));
            int ks = nt >> 1, hf = (nt & 1) * 2;
            aPh[ks][hf] = h01; aPh[ks][hf + 1] = h23;
            aPl[ks][hf] = l01; aPl[ks][hf + 1] = l23;
        }
        rs0 += __shfl_xor_sync(0xffffffffu, rs0, 1);
        rs0 += __shfl_xor_sync(0xffffffffu, rs0, 2);
        rs1 += __shfl_xor_sync(0xffffffffu, rs1, 1);
        rs1 += __shfl_xor_sync(0xffffffffu, rs1, 2);
        l0 = l0 * c0 + rs0;
        l1 = l1 * c1 + rs1;
#pragma unroll
        for (int nt = 0; nt < 8; nt++) {
            O[nt][0] *= c0; O[nt][1] *= c0;
            O[nt][2] *= c1; O[nt][3] *= c1;
        }

        // pending: V(t), K(t+1), V(t+1). Wait V(t).
        CP_WAITG(2);
        __syncthreads();

        // ---- O += P V (2-pass: Phi*Vh + Plo*Vh), V frags via ldmatrix.trans
#pragma unroll
        for (int ks = 0; ks < 4; ks++) {
            uint32_t vf[8][2];
            int kvrow = ks * 16 + (lane & 15);
            uint32_t rsw = kvrow * 128;
#pragma unroll
            for (int p = 0; p < 4; p++) {
                int dseg = 2 * p + (lane >> 4);
                uint32_t addr = stg + 8192 + rsw + ((dseg ^ (kvrow & 7)) << 4);
                ldsm4t(&vf[2 * p][0], addr);
            }
#pragma unroll
            for (int nt = 0; nt < 8; nt++) {
                mma16816h(O[nt], aPh[ks], vf[nt]);
                mma16816h(O[nt], aPl[ks], vf[nt]);
            }
        }
    }

    // ---- normalize + write out[b][l][h*64+d]
    float i0 = 1.f / l0, i1 = 1.f / l1;
    size_t r0 = (size_t)(b * LL + qb + wm + gid);
#pragma unroll
    for (int nt = 0; nt < 8; nt++) {
        int d = h * HDIM + nt * 8 + 2 * tg;
        *(float2*)(out + r0 * DD + d) = make_float2(O[nt][0] * i0, O[nt][1] * i0);
        *(float2*)(out + (r0 + 8) * DD + d) = make_float2(O[nt][2] * i1, O[nt][3] * i1);
    }
}

// ---------------------------------------------------------------------------
extern "C" void kernel_launch(void* const* d_in, const int* in_sizes, int n_in,
                              void* d_out, int out_size)
{
    const float* x    = (const float*)d_in[0];
    const float* w_in = (const float*)d_in[1];
    const float* off  = (const float*)d_in[2];
    const float* amp  = (const float*)d_in[3];
    const float* shp  = (const float*)d_in[4];
    float* out = (float*)d_out;

    // converts + scores in one launch (scores ride as 128 tail blocks)
    convert2_kernel<<<MTOT + D3 + HH * 8, 256>>>(x, w_in, off, amp, shp);

    {
        const int smem_bytes = 3 * STG_BYTES;  // 98304
        cudaFuncSetAttribute(proj_mma, cudaFuncAttributeMaxDynamicSharedMemorySize,
                             smem_bytes);
        dim3 grid(D3 / 128, MTOT / 128);
        proj_mma<<<grid, 256, smem_bytes>>>();
    }

    {
        const int smem_bytes = 65536 + 2 * 192 * 4;  // 67072
        cudaFuncSetAttribute(attn_mma, cudaFuncAttributeMaxDynamicSharedMemorySize,
                             smem_bytes);
        dim3 agrid(LL / 128, HH, BB);
        attn_mma<<<agrid, 256, smem_bytes>>>(out);
    }
}

// round 16
// speedup vs baseline: 1.4192x; 1.4192x over previous
#include <cuda_runtime.h>
#include <cuda_bf16.h>
#include <cuda_fp16.h>
#include <math.h>
#include <stdint.h>

#define BB 2
#define LL 2048
#define DD 1024
#define HH 16
#define HDIM 64
#define D3 3072
#define RLEN 4095   // 2*L - 1
#define MTOT 4096   // B*L
#define K2 2048     // hi|lo concatenated K

// Scratch (no allocation allowed)
__device__ float g_scores[HH * RLEN];
__device__ __align__(1024) __nv_bfloat16 g_Abig[(size_t)MTOT * K2];  // x  hi|lo
__device__ __align__(1024) __nv_bfloat16 g_Bbig[(size_t)D3 * K2];    // w  hi|lo
// Per-head fp16 tensors: [b][h][l][64]. Q exact (hi+lo); K,V single fp16.
#define HSZ ((size_t)BB * HH * LL * HDIM)
__device__ __align__(1024) __half g_Qh[HSZ];
__device__ __align__(1024) __half g_Ql[HSZ];
__device__ __align__(1024) __half g_Kh[HSZ];
__device__ __align__(1024) __half g_Vh[HSZ];
__device__ __align__(1024) __half g_Dump[HSZ];  // lo-half sink for K/V (unused data)

__device__ __forceinline__ uint32_t smem_to_u32(const void* p) {
    uint32_t a;
    asm("{ .reg .u64 t; cvta.to.shared.u64 t, %1; cvt.u32.u64 %0, t; }"
        : "=r"(a) : "l"(p));
    return a;
}
#define CP16(dst, src) \
    asm volatile("cp.async.cg.shared.global [%0], [%1], 16;" :: "r"(dst), "l"(src))
#define CP_COMMIT() asm volatile("cp.async.commit_group;" ::: "memory")
#define CP_WAITG(n) asm volatile("cp.async.wait_group %0;" :: "n"(n) : "memory")

__device__ __forceinline__ void ldsm4(uint32_t* r, uint32_t addr) {
    asm volatile("ldmatrix.sync.aligned.m8n8.x4.shared.b16 {%0, %1, %2, %3}, [%4];"
                 : "=r"(r[0]), "=r"(r[1]), "=r"(r[2]), "=r"(r[3]) : "r"(addr));
}
__device__ __forceinline__ void ldsm4t(uint32_t* r, uint32_t addr) {
    asm volatile("ldmatrix.sync.aligned.m8n8.x4.trans.shared.b16 {%0, %1, %2, %3}, [%4];"
                 : "=r"(r[0]), "=r"(r[1]), "=r"(r[2]), "=r"(r[3]) : "r"(addr));
}
__device__ __forceinline__ void mma16816(float* c, const uint32_t* a, const uint32_t* b) {
    asm volatile("mma.sync.aligned.m16n8k16.row.col.f32.bf16.bf16.f32 "
                 "{%0, %1, %2, %3}, {%4, %5, %6, %7}, {%8, %9}, {%0, %1, %2, %3};"
                 : "+f"(c[0]), "+f"(c[1]), "+f"(c[2]), "+f"(c[3])
                 : "r"(a[0]), "r"(a[1]), "r"(a[2]), "r"(a[3]), "r"(b[0]), "r"(b[1]));
}
__device__ __forceinline__ void mma16816h(float* c, const uint32_t* a, const uint32_t* b) {
    asm volatile("mma.sync.aligned.m16n8k16.row.col.f32.f16.f16.f32 "
                 "{%0, %1, %2, %3}, {%4, %5, %6, %7}, {%8, %9}, {%0, %1, %2, %3};"
                 : "+f"(c[0]), "+f"(c[1]), "+f"(c[2]), "+f"(c[3])
                 : "r"(a[0]), "r"(a[1]), "r"(a[2]), "r"(a[3]), "r"(b[0]), "r"(b[1]));
}
// packed f16x2: low half = lo, high half = hi
__device__ __forceinline__ uint32_t packhf(float lo, float hi) {
    uint32_t r;
    asm("cvt.rn.f16x2.f32 %0, %1, %2;" : "=r"(r) : "f"(hi), "f"(lo));
    return r;
}
__device__ __forceinline__ float lowh(uint32_t p) {
    return __half2float(__ushort_as_half((unsigned short)(p & 0xFFFFu)));
}
__device__ __forceinline__ float highh(uint32_t p) {
    return __half2float(__ushort_as_half((unsigned short)(p >> 16)));
}

// ---------------------------------------------------------------------------
// Kernel 1: fused fp32 -> bf16 hi/lo split for x and w_in + TISA bias table
// as 128 tail blocks (one launch). (R13-proven, 15.5us)
// ---------------------------------------------------------------------------
__global__ __launch_bounds__(256) void convert2_kernel(const float* __restrict__ x,
                                                       const float* __restrict__ w,
                                                       const float* __restrict__ off,
                                                       const float* __restrict__ amp,
                                                       const float* __restrict__ shp)
{
    __shared__ float so[16], sa[16], ss[16];
    int blk = blockIdx.x;
    if (blk >= MTOT + D3) {
        int b2 = blk - (MTOT + D3);
        int h = b2 >> 3, slice = b2 & 7;
        if (threadIdx.x < 16) {
            so[threadIdx.x] = off[h * 16 + threadIdx.x];
            sa[threadIdx.x] = amp[h * 16 + threadIdx.x];
            ss[threadIdx.x] = fabsf(shp[h * 16 + threadIdx.x]);
        }
        __syncthreads();
        for (int r = slice * 256 + threadIdx.x; r < RLEN; r += 8 * 256) {
            float rel = (float)(r - (LL - 1));
            float acc = 0.f;
#pragma unroll
            for (int k = 0; k < 16; k++) {
                float d = so[k] - rel;
                acc += sa[k] * expf(-ss[k] * d * d);
            }
            g_scores[h * RLEN + r] = acc;
        }
        return;
    }

    int idx = blk * 256 + threadIdx.x;
    int row = idx >> 8;
    int k = (idx & 255) << 2;
    const float* src;
    __nv_bfloat16* dst;
    int r;
    if (row < MTOT) { src = x; dst = g_Abig; r = row; }
    else            { src = w; dst = g_Bbig; r = row - MTOT; }
    float4 v = *(const float4*)(src + (size_t)r * DD + k);
    __nv_bfloat16 h0 = __float2bfloat16_rn(v.x);
    __nv_bfloat16 h1 = __float2bfloat16_rn(v.y);
    __nv_bfloat16 h2 = __float2bfloat16_rn(v.z);
    __nv_bfloat16 h3 = __float2bfloat16_rn(v.w);
    __nv_bfloat16 l0 = __float2bfloat16_rn(v.x - __bfloat162float(h0));
    __nv_bfloat16 l1 = __float2bfloat16_rn(v.y - __bfloat162float(h1));
    __nv_bfloat16 l2 = __float2bfloat16_rn(v.z - __bfloat162float(h2));
    __nv_bfloat16 l3 = __float2bfloat16_rn(v.w - __bfloat162float(h3));
    __nv_bfloat162* dh = (__nv_bfloat162*)(dst + (size_t)r * K2 + k);
    dh[0] = __nv_bfloat162(h0, h1);
    dh[1] = __nv_bfloat162(h2, h3);
    __nv_bfloat162* dl = (__nv_bfloat162*)(dst + (size_t)r * K2 + DD + k);
    dl[0] = __nv_bfloat162(l0, l1);
    dl[1] = __nv_bfloat162(l2, l3);
}

// ---------------------------------------------------------------------------
// Kernel 2: bf16 HMMA 3-pass split GEMM — FROZEN (R13 config, measured 213us;
// the only register-feasible proj at 2 CTAs/SM — R8/R9/R12/R14 all spilled).
// ---------------------------------------------------------------------------
#define NCHUNK 48
#define STG_BYTES 32768

__device__ __forceinline__ void load_chunk(uint32_t sA, uint32_t sB,
                                           const __nv_bfloat16* __restrict__ gA,
                                           const __nv_bfloat16* __restrict__ gB,
                                           int bm, int bn, int ka, int kb, int tid)
{
#pragma unroll
    for (int i = 0; i < 4; i++) {
        int s = tid + i * 256;
        int row = s >> 3, kseg = s & 7;
        uint32_t dst = sA + row * 128 + ((kseg ^ (row & 7)) << 4);
        const void* src = gA + (size_t)(bm + row) * K2 + ka + kseg * 8;
        CP16(dst, src);
    }
#pragma unroll
    for (int i = 0; i < 4; i++) {
        int s = tid + i * 256;
        int row = s >> 3, kseg = s & 7;
        uint32_t dst = sB + row * 128 + ((kseg ^ (row & 7)) << 4);
        const void* src = gB + (size_t)(bn + row) * K2 + kb + kseg * 8;
        CP16(dst, src);
    }
    CP_COMMIT();
}

__global__ __launch_bounds__(256, 2) void proj_mma()
{
    extern __shared__ char smem[];
    const uint32_t sbase = smem_to_u32(smem);
    const int tid = threadIdx.x;
    const int wid = tid >> 5, lane = tid & 31;
    const int bm = blockIdx.y * 128, bn = blockIdx.x * 128;
    const int wm = (wid >> 1) * 32;
    const int wn = (wid & 1) * 64;

    float acc[2][8][4];
#pragma unroll
    for (int mt = 0; mt < 2; mt++)
#pragma unroll
        for (int nt = 0; nt < 8; nt++)
#pragma unroll
            for (int c = 0; c < 4; c++) acc[mt][nt][c] = 0.f;

    auto kamap = [](int t, int& ka, int& kb) {
        int pass = t >> 4, kt = t & 15;
        ka = (pass == 2) ? (DD + kt * 64) : (kt * 64);
        kb = (pass == 1) ? (DD + kt * 64) : (kt * 64);
    };

    {
        int ka, kb;
        kamap(0, ka, kb);
        load_chunk(sbase, sbase + 16384, g_Abig, g_Bbig, bm, bn, ka, kb, tid);
        kamap(1, ka, kb);
        load_chunk(sbase + STG_BYTES, sbase + STG_BYTES + 16384, g_Abig, g_Bbig,
                   bm, bn, ka, kb, tid);
    }

    for (int t = 0; t < NCHUNK; t++) {
        CP_WAITG(1);
        __syncthreads();

        if (t + 2 < NCHUNK) {
            int ka, kb;
            kamap(t + 2, ka, kb);
            uint32_t s = sbase + ((t + 2) % 3) * STG_BYTES;
            load_chunk(s, s + 16384, g_Abig, g_Bbig, bm, bn, ka, kb, tid);
        } else {
            CP_COMMIT();
        }

        const uint32_t sA = sbase + (t % 3) * STG_BYTES;
        const uint32_t sB = sA + 16384;

#pragma unroll
        for (int kk = 0; kk < 4; kk++) {
            uint32_t a[2][4];
#pragma unroll
            for (int mt = 0; mt < 2; mt++) {
                int row = wm + mt * 16 + (lane & 15);
                int kseg = kk * 2 + (lane >> 4);
                uint32_t addr = sA + row * 128 + ((kseg ^ (row & 7)) << 4);
                ldsm4(a[mt], addr);
            }
            uint32_t b[8][2];
#pragma unroll
            for (int p = 0; p < 4; p++) {
                int row = wn + p * 16 + (lane & 7) + ((lane >> 4) << 3);
                int kseg = kk * 2 + ((lane >> 3) & 1);
                uint32_t addr = sB + row * 128 + ((kseg ^ (row & 7)) << 4);
                ldsm4(&b[2 * p][0], addr);
            }
#pragma unroll
            for (int mt = 0; mt < 2; mt++)
#pragma unroll
                for (int nt = 0; nt < 8; nt++)
                    mma16816(acc[mt][nt], a[mt], b[nt]);
        }
        __syncthreads();   // load-bearing: fences ptxas pipelining (reg cap)
    }

    // Epilogue (uniform path, R13-proven shape): fp16 hi/lo packs + ptr select.
#pragma unroll
    for (int mt = 0; mt < 2; mt++) {
        int row0 = bm + wm + mt * 16 + (lane >> 2);
        int b = row0 >> 11;
        int l = row0 & 2047;
#pragma unroll
        for (int nt = 0; nt < 8; nt++) {
            int col = bn + wn + nt * 8 + (lane & 3) * 2;
            int ty = col >> 10;            // 0=k, 1=v, 2=q
            int h = (col >> 6) & 15;
            int d = col & 63;
            float sc = (ty == 2) ? 0.125f : 1.0f;
            float v0 = acc[mt][nt][0] * sc, v1 = acc[mt][nt][1] * sc;
            float v2 = acc[mt][nt][2] * sc, v3 = acc[mt][nt][3] * sc;
            uint32_t h01 = packhf(v0, v1), h23 = packhf(v2, v3);
            uint32_t l01 = packhf(v0 - lowh(h01), v1 - highh(h01));
            uint32_t l23 = packhf(v2 - lowh(h23), v3 - highh(h23));
            __half *dh, *dl;
            if (ty == 0)      { dh = g_Kh; dl = g_Dump; }
            else if (ty == 1) { dh = g_Vh; dl = g_Dump; }
            else              { dh = g_Qh; dl = g_Ql; }
            size_t base0 = ((size_t)(b * HH + h) * LL + l) * HDIM + d;
            size_t base1 = base0 + 8 * HDIM;
            *(uint32_t*)(dh + base0) = h01;
            *(uint32_t*)(dl + base0) = l01;
            *(uint32_t*)(dh + base1) = h23;
            *(uint32_t*)(dl + base1) = l23;
        }
    }
}

// ---------------------------------------------------------------------------
// Kernel 3: fp16 HMMA flash attention, 2 CTAs/SM.
// QK SINGLE-pass: Qhi*Kh (Q-lo term dropped: contributes ~2.4e-4, budget OK).
// PV 2-pass: (Phi+Plo)*Vh, P split in registers.
// smem layout unchanged from R13 (Ql region kept; contents unused).
// ---------------------------------------------------------------------------
#define ASTG 16384

__device__ __forceinline__ void attn_load_k(uint32_t sbase, int stage, int bh,
                                            int kb, int tid)
{
    uint32_t stg = sbase + stage * ASTG;
#pragma unroll
    for (int i = 0; i < 2; i++) {
        int s = tid + i * 256;
        int row = s >> 3, kseg = s & 7;
        uint32_t dst = stg + row * 128 + ((kseg ^ (row & 7)) << 4);
        const void* src = g_Kh + ((size_t)bh * LL + kb + row) * HDIM + kseg * 8;
        CP16(dst, src);
    }
    CP_COMMIT();
}
__device__ __forceinline__ void attn_load_v(uint32_t sbase, int stage, int bh,
                                            int kb, int tid)
{
    uint32_t stg = sbase + stage * ASTG + 8192;
#pragma unroll
    for (int i = 0; i < 2; i++) {
        int s = tid + i * 256;
        int row = s >> 3, kseg = s & 7;
        uint32_t dst = stg + row * 128 + ((kseg ^ (row & 7)) << 4);
        const void* src = g_Vh + ((size_t)bh * LL + kb + row) * HDIM + kseg * 8;
        CP16(dst, src);
    }
    CP_COMMIT();
}

__global__ __launch_bounds__(256, 2) void attn_mma(float* __restrict__ out)
{
    extern __shared__ char smem[];
    const uint32_t sbase = smem_to_u32(smem);
    const uint32_t sQ = sbase + 32768;     // Q hi @ +0, Q lo @ +16384 (unused)
    float* sb = (float*)(smem + 65536);    // [2][192]
    const int tid = threadIdx.x;
    const int wid = tid >> 5, lane = tid & 31;
    const int gid = lane >> 2, tg = lane & 3;
    const int qb = blockIdx.x * 128;
    const int h = blockIdx.y, b = blockIdx.z;
    const int bh = b * HH + h;
    const int wm = wid * 16;
    const float* srow = g_scores + h * RLEN;

    // --- Prologue: Q (hi/lo) into dedicated smem; K0/V0 issued right behind.
#pragma unroll
    for (int i = 0; i < 8; i++) {
        const int comp = i >> 2;
        int s = tid + (i & 3) * 256;
        int row = s >> 3, kseg = s & 7;
        const __half* gb = comp ? g_Ql : g_Qh;
        uint32_t dst = sQ + comp * 16384 + row * 128 + ((kseg ^ (row & 7)) << 4);
        const void* src = gb + ((size_t)bh * LL + qb + row) * HDIM + kseg * 8;
        CP16(dst, src);
    }
    CP_COMMIT();                         // group: Q
    attn_load_k(sbase, 0, bh, 0, tid);   // group: K0
    attn_load_v(sbase, 0, bh, 0, tid);   // group: V0
    if (tid < 192) {
        int sidx = qb + 1984 + tid;
        sb[tid] = srow[min(sidx, RLEN - 1)];
    }
    CP_WAITG(2);                         // Q done (K0/V0 may be pending)
    __syncthreads();

    uint32_t aQh[4][4];
#pragma unroll
    for (int ks = 0; ks < 4; ks++) {
        int row = wm + (lane & 15);
        int kseg = ks * 2 + (lane >> 4);
        ldsm4(aQh[ks], sQ + row * 128 + ((kseg ^ (row & 7)) << 4));
    }

    float O[8][4];
#pragma unroll
    for (int nt = 0; nt < 8; nt++)
#pragma unroll
        for (int c = 0; c < 4; c++) O[nt][c] = 0.f;
    float m0 = -1e30f, m1 = -1e30f, l0 = 0.f, l1 = 0.f;

    for (int t = 0; t < LL / 64; t++) {
        // pending here: K(t), V(t). Wait K only.
        CP_WAITG(1);
        __syncthreads();
        const uint32_t stg = sbase + (t & 1) * ASTG;
        const float* sbt = sb + (t & 1) * 192;

        if (t + 1 < LL / 64) {
            attn_load_k(sbase, (t + 1) & 1, bh, (t + 1) * 64, tid);
            attn_load_v(sbase, (t + 1) & 1, bh, (t + 1) * 64, tid);
            if (tid < 192) {
                int sidx = qb - (t + 1) * 64 + 1984 + tid;
                sb[((t + 1) & 1) * 192 + tid] = srow[min(sidx, RLEN - 1)];
            }
        } else {
            CP_COMMIT();
            CP_COMMIT();
        }

        // ---- S = Q K^T (single pass: Qhi*Kh), fp32 accum
        float S[8][4];
#pragma unroll
        for (int nt = 0; nt < 8; nt++)
#pragma unroll
            for (int c = 0; c < 4; c++) S[nt][c] = 0.f;

#pragma unroll
        for (int kk = 0; kk < 4; kk++) {
            uint32_t kf[8][2];
            int krow = (lane & 7) + ((lane >> 4) << 3);
            int kkseg = kk * 2 + ((lane >> 3) & 1);
#pragma unroll
            for (int p = 0; p < 4; p++) {
                int row = krow + p * 16;
                uint32_t addr = stg + row * 128 + ((kkseg ^ (row & 7)) << 4);
                ldsm4(&kf[2 * p][0], addr);
            }
#pragma unroll
            for (int nt = 0; nt < 8; nt++)
                mma16816h(S[nt], aQh[kk], kf[nt]);
        }

        // ---- bias + online softmax (V load still in flight underneath)
        const int jbase = wm + gid + 63 - 2 * tg;
        float mx0 = -1e30f, mx1 = -1e30f;
#pragma unroll
        for (int nt = 0; nt < 8; nt++) {
            int j = jbase - 8 * nt;
            S[nt][0] += sbt[j];
            S[nt][1] += sbt[j - 1];
            S[nt][2] += sbt[j + 8];
            S[nt][3] += sbt[j + 7];
            mx0 = fmaxf(mx0, fmaxf(S[nt][0], S[nt][1]));
            mx1 = fmaxf(mx1, fmaxf(S[nt][2], S[nt][3]));
        }
        mx0 = fmaxf(mx0, __shfl_xor_sync(0xffffffffu, mx0, 1));
        mx0 = fmaxf(mx0, __shfl_xor_sync(0xffffffffu, mx0, 2));
        mx1 = fmaxf(mx1, __shfl_xor_sync(0xffffffffu, mx1, 1));
        mx1 = fmaxf(mx1, __shfl_xor_sync(0xffffffffu, mx1, 2));
        float nm0 = fmaxf(m0, mx0), nm1 = fmaxf(m1, mx1);
        float c0 = __expf(m0 - nm0), c1 = __expf(m1 - nm1);
        m0 = nm0; m1 = nm1;

        float rs0 = 0.f, rs1 = 0.f;
        uint32_t aPh[4][4], aPl[4][4];
#pragma unroll
        for (int nt = 0; nt < 8; nt++) {
            float p0 = __expf(S[nt][0] - nm0);
            float p1 = __expf(S[nt][1] - nm0);
            float p2 = __expf(S[nt][2] - nm1);
            float p3 = __expf(S[nt][3] - nm1);
            rs0 += p0 + p1;
            rs1 += p2 + p3;
            uint32_t h01 = packhf(p0, p1), h23 = packhf(p2, p3);
            uint32_t l01 = packhf(p0 - lowh(h01), p1 - highh(h01));
            uint32_t l23 = packhf(p2 - lowh(h23), p3 - highh(h23));
            int ks = nt >> 1, hf = (nt & 1) * 2;
            aPh[ks][hf] = h01; aPh[ks][hf + 1] = h23;
            aPl[ks][hf] = l01; aPl[ks][hf + 1] = l23;
        }
        rs0 += __shfl_xor_sync(0xffffffffu, rs0, 1);
        rs0 += __shfl_xor_sync(0xffffffffu, rs0, 2);
        rs1 += __shfl_xor_sync(0xffffffffu, rs1, 1);
        rs1 += __shfl_xor_sync(0xffffffffu, rs1, 2);
        l0 = l0 * c0 + rs0;
        l1 = l1 * c1 + rs1;
#pragma unroll
        for (int nt = 0; nt < 8; nt++) {
            O[nt][0] *= c0; O[nt][1] *= c0;
            O[nt][2] *= c1; O[nt][3] *= c1;
        }

        // pending: V(t), K(t+1), V(t+1). Wait V(t).
        CP_WAITG(2);
        __syncthreads();

        // ---- O += P V (2-pass: Phi*Vh + Plo*Vh), V frags via ldmatrix.trans
#pragma unroll
        for (int ks = 0; ks < 4; ks++) {
            uint32_t vf[8][2];
            int kvrow = ks * 16 + (lane & 15);
            uint32_t rsw = kvrow * 128;
#pragma unroll
            for (int p = 0; p < 4; p++) {
                int dseg = 2 * p + (lane >> 4);
                uint32_t addr = stg + 8192 + rsw + ((dseg ^ (kvrow & 7)) << 4);
                ldsm4t(&vf[2 * p][0], addr);
            }
#pragma unroll
            for (int nt = 0; nt < 8; nt++) {
                mma16816h(O[nt], aPh[ks], vf[nt]);
                mma16816h(O[nt], aPl[ks], vf[nt]);
            }
        }
    }

    // ---- normalize + write out[b][l][h*64+d]
    float i0 = 1.f / l0, i1 = 1.f / l1;
    size_t r0 = (size_t)(b * LL + qb + wm + gid);
#pragma unroll
    for (int nt = 0; nt < 8; nt++) {
        int d = h * HDIM + nt * 8 + 2 * tg;
        *(float2*)(out + r0 * DD + d) = make_float2(O[nt][0] * i0, O[nt][1] * i0);
        *(float2*)(out + (r0 + 8) * DD + d) = make_float2(O[nt][2] * i1, O[nt][3] * i1);
    }
}

// ---------------------------------------------------------------------------
extern "C" void kernel_launch(void* const* d_in, const int* in_sizes, int n_in,
                              void* d_out, int out_size)
{
    const float* x    = (const float*)d_in[0];
    const float* w_in = (const float*)d_in[1];
    const float* off  = (const float*)d_in[2];
    const float* amp  = (const float*)d_in[3];
    const float* shp  = (const float*)d_in[4];
    float* out = (float*)d_out;

    // converts + scores in one launch (scores ride as 128 tail blocks)
    convert2_kernel<<<MTOT + D3 + HH * 8, 256>>>(x, w_in, off, amp, shp);

    {
        const int smem_bytes = 3 * STG_BYTES;  // 98304
        cudaFuncSetAttribute(proj_mma, cudaFuncAttributeMaxDynamicSharedMemorySize,
                             smem_bytes);
        dim3 grid(D3 / 128, MTOT / 128);
        proj_mma<<<grid, 256, smem_bytes>>>();
    }

    {
        const int smem_bytes = 65536 + 2 * 192 * 4;  // 67072
        cudaFuncSetAttribute(attn_mma, cudaFuncAttributeMaxDynamicSharedMemorySize,
                             smem_bytes);
        dim3 agrid(LL / 128, HH, BB);
        attn_mma<<<agrid, 256, smem_bytes>>>(out);
    }
}

// round 17
// speedup vs baseline: 1.5753x; 1.1100x over previous
#include <cuda_runtime.h>
#include <cuda_bf16.h>
#include <cuda_fp16.h>
#include <math.h>
#include <stdint.h>

#define BB 2
#define LL 2048
#define DD 1024
#define HH 16
#define HDIM 64
#define D3 3072
#define RLEN 4095   // 2*L - 1
#define MTOT 4096   // B*L
#define K2 2048     // hi|lo concatenated K

// Scratch (no allocation allowed)
__device__ float g_scores[HH * RLEN];
__device__ __align__(1024) __nv_bfloat16 g_Abig[(size_t)MTOT * K2];  // x  hi|lo
__device__ __align__(1024) __nv_bfloat16 g_Bbig[(size_t)D3 * K2];    // w  hi|lo
// Per-head fp16 tensors: [b][h][l][64].
#define HSZ ((size_t)BB * HH * LL * HDIM)
__device__ __align__(1024) __half g_Qh[HSZ];
__device__ __align__(1024) __half g_Ql[HSZ];   // written by proj (frozen), unused
__device__ __align__(1024) __half g_Kh[HSZ];
__device__ __align__(1024) __half g_Vh[HSZ];
__device__ __align__(1024) __half g_Dump[HSZ];  // lo-half sink for K/V (unused data)

__device__ __forceinline__ uint32_t smem_to_u32(const void* p) {
    uint32_t a;
    asm("{ .reg .u64 t; cvta.to.shared.u64 t, %1; cvt.u32.u64 %0, t; }"
        : "=r"(a) : "l"(p));
    return a;
}
#define CP16(dst, src) \
    asm volatile("cp.async.cg.shared.global [%0], [%1], 16;" :: "r"(dst), "l"(src))
#define CP_COMMIT() asm volatile("cp.async.commit_group;" ::: "memory")
#define CP_WAITG(n) asm volatile("cp.async.wait_group %0;" :: "n"(n) : "memory")

__device__ __forceinline__ void ldsm4(uint32_t* r, uint32_t addr) {
    asm volatile("ldmatrix.sync.aligned.m8n8.x4.shared.b16 {%0, %1, %2, %3}, [%4];"
                 : "=r"(r[0]), "=r"(r[1]), "=r"(r[2]), "=r"(r[3]) : "r"(addr));
}
__device__ __forceinline__ void ldsm4t(uint32_t* r, uint32_t addr) {
    asm volatile("ldmatrix.sync.aligned.m8n8.x4.trans.shared.b16 {%0, %1, %2, %3}, [%4];"
                 : "=r"(r[0]), "=r"(r[1]), "=r"(r[2]), "=r"(r[3]) : "r"(addr));
}
__device__ __forceinline__ void mma16816(float* c, const uint32_t* a, const uint32_t* b) {
    asm volatile("mma.sync.aligned.m16n8k16.row.col.f32.bf16.bf16.f32 "
                 "{%0, %1, %2, %3}, {%4, %5, %6, %7}, {%8, %9}, {%0, %1, %2, %3};"
                 : "+f"(c[0]), "+f"(c[1]), "+f"(c[2]), "+f"(c[3])
                 : "r"(a[0]), "r"(a[1]), "r"(a[2]), "r"(a[3]), "r"(b[0]), "r"(b[1]));
}
__device__ __forceinline__ void mma16816h(float* c, const uint32_t* a, const uint32_t* b) {
    asm volatile("mma.sync.aligned.m16n8k16.row.col.f32.f16.f16.f32 "
                 "{%0, %1, %2, %3}, {%4, %5, %6, %7}, {%8, %9}, {%0, %1, %2, %3};"
                 : "+f"(c[0]), "+f"(c[1]), "+f"(c[2]), "+f"(c[3])
                 : "r"(a[0]), "r"(a[1]), "r"(a[2]), "r"(a[3]), "r"(b[0]), "r"(b[1]));
}
// packed f16x2: low half = lo, high half = hi
__device__ __forceinline__ uint32_t packhf(float lo, float hi) {
    uint32_t r;
    asm("cvt.rn.f16x2.f32 %0, %1, %2;" : "=r"(r) : "f"(hi), "f"(lo));
    return r;
}
__device__ __forceinline__ float lowh(uint32_t p) {
    return __half2float(__ushort_as_half((unsigned short)(p & 0xFFFFu)));
}
__device__ __forceinline__ float highh(uint32_t p) {
    return __half2float(__ushort_as_half((unsigned short)(p >> 16)));
}

// ---------------------------------------------------------------------------
// Kernel 1: fused fp32 -> bf16 hi/lo split for x and w_in + TISA bias table
// as 128 tail blocks (one launch). (R13-proven)
// ---------------------------------------------------------------------------
__global__ __launch_bounds__(256) void convert2_kernel(const float* __restrict__ x,
                                                       const float* __restrict__ w,
                                                       const float* __restrict__ off,
                                                       const float* __restrict__ amp,
                                                       const float* __restrict__ shp)
{
    __shared__ float so[16], sa[16], ss[16];
    int blk = blockIdx.x;
    if (blk >= MTOT + D3) {
        int b2 = blk - (MTOT + D3);
        int h = b2 >> 3, slice = b2 & 7;
        if (threadIdx.x < 16) {
            so[threadIdx.x] = off[h * 16 + threadIdx.x];
            sa[threadIdx.x] = amp[h * 16 + threadIdx.x];
            ss[threadIdx.x] = fabsf(shp[h * 16 + threadIdx.x]);
        }
        __syncthreads();
        for (int r = slice * 256 + threadIdx.x; r < RLEN; r += 8 * 256) {
            float rel = (float)(r - (LL - 1));
            float acc = 0.f;
#pragma unroll
            for (int k = 0; k < 16; k++) {
                float d = so[k] - rel;
                acc += sa[k] * expf(-ss[k] * d * d);
            }
            g_scores[h * RLEN + r] = acc;
        }
        return;
    }

    int idx = blk * 256 + threadIdx.x;
    int row = idx >> 8;
    int k = (idx & 255) << 2;
    const float* src;
    __nv_bfloat16* dst;
    int r;
    if (row < MTOT) { src = x; dst = g_Abig; r = row; }
    else            { src = w; dst = g_Bbig; r = row - MTOT; }
    float4 v = *(const float4*)(src + (size_t)r * DD + k);
    __nv_bfloat16 h0 = __float2bfloat16_rn(v.x);
    __nv_bfloat16 h1 = __float2bfloat16_rn(v.y);
    __nv_bfloat16 h2 = __float2bfloat16_rn(v.z);
    __nv_bfloat16 h3 = __float2bfloat16_rn(v.w);
    __nv_bfloat16 l0 = __float2bfloat16_rn(v.x - __bfloat162float(h0));
    __nv_bfloat16 l1 = __float2bfloat16_rn(v.y - __bfloat162float(h1));
    __nv_bfloat16 l2 = __float2bfloat16_rn(v.z - __bfloat162float(h2));
    __nv_bfloat16 l3 = __float2bfloat16_rn(v.w - __bfloat162float(h3));
    __nv_bfloat162* dh = (__nv_bfloat162*)(dst + (size_t)r * K2 + k);
    dh[0] = __nv_bfloat162(h0, h1);
    dh[1] = __nv_bfloat162(h2, h3);
    __nv_bfloat162* dl = (__nv_bfloat162*)(dst + (size_t)r * K2 + DD + k);
    dl[0] = __nv_bfloat162(l0, l1);
    dl[1] = __nv_bfloat162(l2, l3);
}

// ---------------------------------------------------------------------------
// Kernel 2: bf16 HMMA 3-pass split GEMM — FROZEN (R13 config, measured 213us;
// the only register-feasible proj at 2 CTAs/SM — R8/R9/R12/R14 all spilled).
// ---------------------------------------------------------------------------
#define NCHUNK 48
#define STG_BYTES 32768

__device__ __forceinline__ void load_chunk(uint32_t sA, uint32_t sB,
                                           const __nv_bfloat16* __restrict__ gA,
                                           const __nv_bfloat16* __restrict__ gB,
                                           int bm, int bn, int ka, int kb, int tid)
{
#pragma unroll
    for (int i = 0; i < 4; i++) {
        int s = tid + i * 256;
        int row = s >> 3, kseg = s & 7;
        uint32_t dst = sA + row * 128 + ((kseg ^ (row & 7)) << 4);
        const void* src = gA + (size_t)(bm + row) * K2 + ka + kseg * 8;
        CP16(dst, src);
    }
#pragma unroll
    for (int i = 0; i < 4; i++) {
        int s = tid + i * 256;
        int row = s >> 3, kseg = s & 7;
        uint32_t dst = sB + row * 128 + ((kseg ^ (row & 7)) << 4);
        const void* src = gB + (size_t)(bn + row) * K2 + kb + kseg * 8;
        CP16(dst, src);
    }
    CP_COMMIT();
}

__global__ __launch_bounds__(256, 2) void proj_mma()
{
    extern __shared__ char smem[];
    const uint32_t sbase = smem_to_u32(smem);
    const int tid = threadIdx.x;
    const int wid = tid >> 5, lane = tid & 31;
    const int bm = blockIdx.y * 128, bn = blockIdx.x * 128;
    const int wm = (wid >> 1) * 32;
    const int wn = (wid & 1) * 64;

    float acc[2][8][4];
#pragma unroll
    for (int mt = 0; mt < 2; mt++)
#pragma unroll
        for (int nt = 0; nt < 8; nt++)
#pragma unroll
            for (int c = 0; c < 4; c++) acc[mt][nt][c] = 0.f;

    auto kamap = [](int t, int& ka, int& kb) {
        int pass = t >> 4, kt = t & 15;
        ka = (pass == 2) ? (DD + kt * 64) : (kt * 64);
        kb = (pass == 1) ? (DD + kt * 64) : (kt * 64);
    };

    {
        int ka, kb;
        kamap(0, ka, kb);
        load_chunk(sbase, sbase + 16384, g_Abig, g_Bbig, bm, bn, ka, kb, tid);
        kamap(1, ka, kb);
        load_chunk(sbase + STG_BYTES, sbase + STG_BYTES + 16384, g_Abig, g_Bbig,
                   bm, bn, ka, kb, tid);
    }

    for (int t = 0; t < NCHUNK; t++) {
        CP_WAITG(1);
        __syncthreads();

        if (t + 2 < NCHUNK) {
            int ka, kb;
            kamap(t + 2, ka, kb);
            uint32_t s = sbase + ((t + 2) % 3) * STG_BYTES;
            load_chunk(s, s + 16384, g_Abig, g_Bbig, bm, bn, ka, kb, tid);
        } else {
            CP_COMMIT();
        }

        const uint32_t sA = sbase + (t % 3) * STG_BYTES;
        const uint32_t sB = sA + 16384;

#pragma unroll
        for (int kk = 0; kk < 4; kk++) {
            uint32_t a[2][4];
#pragma unroll
            for (int mt = 0; mt < 2; mt++) {
                int row = wm + mt * 16 + (lane & 15);
                int kseg = kk * 2 + (lane >> 4);
                uint32_t addr = sA + row * 128 + ((kseg ^ (row & 7)) << 4);
                ldsm4(a[mt], addr);
            }
            uint32_t b[8][2];
#pragma unroll
            for (int p = 0; p < 4; p++) {
                int row = wn + p * 16 + (lane & 7) + ((lane >> 4) << 3);
                int kseg = kk * 2 + ((lane >> 3) & 1);
                uint32_t addr = sB + row * 128 + ((kseg ^ (row & 7)) << 4);
                ldsm4(&b[2 * p][0], addr);
            }
#pragma unroll
            for (int mt = 0; mt < 2; mt++)
#pragma unroll
                for (int nt = 0; nt < 8; nt++)
                    mma16816(acc[mt][nt], a[mt], b[nt]);
        }
        __syncthreads();   // load-bearing: fences ptxas pipelining (reg cap)
    }

    // Epilogue (uniform path, R13-proven shape): fp16 hi/lo packs + ptr select.
#pragma unroll
    for (int mt = 0; mt < 2; mt++) {
        int row0 = bm + wm + mt * 16 + (lane >> 2);
        int b = row0 >> 11;
        int l = row0 & 2047;
#pragma unroll
        for (int nt = 0; nt < 8; nt++) {
            int col = bn + wn + nt * 8 + (lane & 3) * 2;
            int ty = col >> 10;            // 0=k, 1=v, 2=q
            int h = (col >> 6) & 15;
            int d = col & 63;
            float sc = (ty == 2) ? 0.125f : 1.0f;
            float v0 = acc[mt][nt][0] * sc, v1 = acc[mt][nt][1] * sc;
            float v2 = acc[mt][nt][2] * sc, v3 = acc[mt][nt][3] * sc;
            uint32_t h01 = packhf(v0, v1), h23 = packhf(v2, v3);
            uint32_t l01 = packhf(v0 - lowh(h01), v1 - highh(h01));
            uint32_t l23 = packhf(v2 - lowh(h23), v3 - highh(h23));
            __half *dh, *dl;
            if (ty == 0)      { dh = g_Kh; dl = g_Dump; }
            else if (ty == 1) { dh = g_Vh; dl = g_Dump; }
            else              { dh = g_Qh; dl = g_Ql; }
            size_t base0 = ((size_t)(b * HH + h) * LL + l) * HDIM + d;
            size_t base1 = base0 + 8 * HDIM;
            *(uint32_t*)(dh + base0) = h01;
            *(uint32_t*)(dl + base0) = l01;
            *(uint32_t*)(dh + base1) = h23;
            *(uint32_t*)(dl + base1) = l23;
        }
    }
}

// ---------------------------------------------------------------------------
// Kernel 3: fp16 HMMA flash attention, 2 CTAs/SM.
// QK single-pass: Qhi*Kh. PV single-pass: P(fp16)*Vh.
// Error model: QK drop ~2.4e-4 + PV fp16 rounding ~2.4e-4 + upstream ~1e-4,
// quadrature ~3.4e-4 vs 1e-3 gate.
// smem: KV stage s at s*16384 (Kh 8KB | Vh 8KB); Q hi @32768 (16KB);
//       bias sb[2][192] @49152.
// ---------------------------------------------------------------------------
#define ASTG 16384

__device__ __forceinline__ void attn_load_k(uint32_t sbase, int stage, int bh,
                                            int kb, int tid)
{
    uint32_t stg = sbase + stage * ASTG;
#pragma unroll
    for (int i = 0; i < 2; i++) {
        int s = tid + i * 256;
        int row = s >> 3, kseg = s & 7;
        uint32_t dst = stg + row * 128 + ((kseg ^ (row & 7)) << 4);
        const void* src = g_Kh + ((size_t)bh * LL + kb + row) * HDIM + kseg * 8;
        CP16(dst, src);
    }
    CP_COMMIT();
}
__device__ __forceinline__ void attn_load_v(uint32_t sbase, int stage, int bh,
                                            int kb, int tid)
{
    uint32_t stg = sbase + stage * ASTG + 8192;
#pragma unroll
    for (int i = 0; i < 2; i++) {
        int s = tid + i * 256;
        int row = s >> 3, kseg = s & 7;
        uint32_t dst = stg + row * 128 + ((kseg ^ (row & 7)) << 4);
        const void* src = g_Vh + ((size_t)bh * LL + kb + row) * HDIM + kseg * 8;
        CP16(dst, src);
    }
    CP_COMMIT();
}

__global__ __launch_bounds__(256, 2) void attn_mma(float* __restrict__ out)
{
    extern __shared__ char smem[];
    const uint32_t sbase = smem_to_u32(smem);
    const uint32_t sQ = sbase + 32768;     // Q hi (16KB)
    float* sb = (float*)(smem + 49152);    // [2][192]
    const int tid = threadIdx.x;
    const int wid = tid >> 5, lane = tid & 31;
    const int gid = lane >> 2, tg = lane & 3;
    const int qb = blockIdx.x * 128;
    const int h = blockIdx.y, b = blockIdx.z;
    const int bh = b * HH + h;
    const int wm = wid * 16;
    const float* srow = g_scores + h * RLEN;

    // --- Prologue: Q-hi into dedicated smem; K0/V0 issued right behind.
#pragma unroll
    for (int i = 0; i < 4; i++) {
        int s = tid + i * 256;
        int row = s >> 3, kseg = s & 7;
        uint32_t dst = sQ + row * 128 + ((kseg ^ (row & 7)) << 4);
        const void* src = g_Qh + ((size_t)bh * LL + qb + row) * HDIM + kseg * 8;
        CP16(dst, src);
    }
    CP_COMMIT();                         // group: Q
    attn_load_k(sbase, 0, bh, 0, tid);   // group: K0
    attn_load_v(sbase, 0, bh, 0, tid);   // group: V0
    if (tid < 192) {
        int sidx = qb + 1984 + tid;
        sb[tid] = srow[min(sidx, RLEN - 1)];
    }
    CP_WAITG(2);                         // Q done (K0/V0 may be pending)
    __syncthreads();

    uint32_t aQh[4][4];
#pragma unroll
    for (int ks = 0; ks < 4; ks++) {
        int row = wm + (lane & 15);
        int kseg = ks * 2 + (lane >> 4);
        ldsm4(aQh[ks], sQ + row * 128 + ((kseg ^ (row & 7)) << 4));
    }

    float O[8][4];
#pragma unroll
    for (int nt = 0; nt < 8; nt++)
#pragma unroll
        for (int c = 0; c < 4; c++) O[nt][c] = 0.f;
    float m0 = -1e30f, m1 = -1e30f, l0 = 0.f, l1 = 0.f;

    for (int t = 0; t < LL / 64; t++) {
        // pending here: K(t), V(t). Wait K only.
        CP_WAITG(1);
        __syncthreads();
        const uint32_t stg = sbase + (t & 1) * ASTG;
        const float* sbt = sb + (t & 1) * 192;

        if (t + 1 < LL / 64) {
            attn_load_k(sbase, (t + 1) & 1, bh, (t + 1) * 64, tid);
            attn_load_v(sbase, (t + 1) & 1, bh, (t + 1) * 64, tid);
            if (tid < 192) {
                int sidx = qb - (t + 1) * 64 + 1984 + tid;
                sb[((t + 1) & 1) * 192 + tid] = srow[min(sidx, RLEN - 1)];
            }
        } else {
            CP_COMMIT();
            CP_COMMIT();
        }

        // ---- S = Q K^T (single pass: Qhi*Kh), fp32 accum
        float S[8][4];
#pragma unroll
        for (int nt = 0; nt < 8; nt++)
#pragma unroll
            for (int c = 0; c < 4; c++) S[nt][c] = 0.f;

#pragma unroll
        for (int kk = 0; kk < 4; kk++) {
            uint32_t kf[8][2];
            int krow = (lane & 7) + ((lane >> 4) << 3);
            int kkseg = kk * 2 + ((lane >> 3) & 1);
#pragma unroll
            for (int p = 0; p < 4; p++) {
                int row = krow + p * 16;
                uint32_t addr = stg + row * 128 + ((kkseg ^ (row & 7)) << 4);
                ldsm4(&kf[2 * p][0], addr);
            }
#pragma unroll
            for (int nt = 0; nt < 8; nt++)
                mma16816h(S[nt], aQh[kk], kf[nt]);
        }

        // ---- bias + online softmax (V load still in flight underneath)
        const int jbase = wm + gid + 63 - 2 * tg;
        float mx0 = -1e30f, mx1 = -1e30f;
#pragma unroll
        for (int nt = 0; nt < 8; nt++) {
            int j = jbase - 8 * nt;
            S[nt][0] += sbt[j];
            S[nt][1] += sbt[j - 1];
            S[nt][2] += sbt[j + 8];
            S[nt][3] += sbt[j + 7];
            mx0 = fmaxf(mx0, fmaxf(S[nt][0], S[nt][1]));
            mx1 = fmaxf(mx1, fmaxf(S[nt][2], S[nt][3]));
        }
        mx0 = fmaxf(mx0, __shfl_xor_sync(0xffffffffu, mx0, 1));
        mx0 = fmaxf(mx0, __shfl_xor_sync(0xffffffffu, mx0, 2));
        mx1 = fmaxf(mx1, __shfl_xor_sync(0xffffffffu, mx1, 1));
        mx1 = fmaxf(mx1, __shfl_xor_sync(0xffffffffu, mx1, 2));
        float nm0 = fmaxf(m0, mx0), nm1 = fmaxf(m1, mx1);
        float c0 = __expf(m0 - nm0), c1 = __expf(m1 - nm1);
        m0 = nm0; m1 = nm1;

        float rs0 = 0.f, rs1 = 0.f;
        uint32_t aPh[4][4];
#pragma unroll
        for (int nt = 0; nt < 8; nt++) {
            float p0 = __expf(S[nt][0] - nm0);
            float p1 = __expf(S[nt][1] - nm0);
            float p2 = __expf(S[nt][2] - nm1);
            float p3 = __expf(S[nt][3] - nm1);
            rs0 += p0 + p1;
            rs1 += p2 + p3;
            uint32_t h01 = packhf(p0, p1), h23 = packhf(p2, p3);
            int ks = nt >> 1, hf = (nt & 1) * 2;
            aPh[ks][hf] = h01; aPh[ks][hf + 1] = h23;
        }
        rs0 += __shfl_xor_sync(0xffffffffu, rs0, 1);
        rs0 += __shfl_xor_sync(0xffffffffu, rs0, 2);
        rs1 += __shfl_xor_sync(0xffffffffu, rs1, 1);
        rs1 += __shfl_xor_sync(0xffffffffu, rs1, 2);
        l0 = l0 * c0 + rs0;
        l1 = l1 * c1 + rs1;
#pragma unroll
        for (int nt = 0; nt < 8; nt++) {
            O[nt][0] *= c0; O[nt][1] *= c0;
            O[nt][2] *= c1; O[nt][3] *= c1;
        }

        // pending: V(t), K(t+1), V(t+1). Wait V(t).
        CP_WAITG(2);
        __syncthreads();

        // ---- O += P V (single pass: P*Vh), V frags via ldmatrix.trans
#pragma unroll
        for (int ks = 0; ks < 4; ks++) {
            uint32_t vf[8][2];
            int kvrow = ks * 16 + (lane & 15);
            uint32_t rsw = kvrow * 128;
#pragma unroll
            for (int p = 0; p < 4; p++) {
                int dseg = 2 * p + (lane >> 4);
                uint32_t addr = stg + 8192 + rsw + ((dseg ^ (kvrow & 7)) << 4);
                ldsm4t(&vf[2 * p][0], addr);
            }
#pragma unroll
            for (int nt = 0; nt < 8; nt++)
                mma16816h(O[nt], aPh[ks], vf[nt]);
        }
    }

    // ---- normalize + write out[b][l][h*64+d]
    float i0 = 1.f / l0, i1 = 1.f / l1;
    size_t r0 = (size_t)(b * LL + qb + wm + gid);
#pragma unroll
    for (int nt = 0; nt < 8; nt++) {
        int d = h * HDIM + nt * 8 + 2 * tg;
        *(float2*)(out + r0 * DD + d) = make_float2(O[nt][0] * i0, O[nt][1] * i0);
        *(float2*)(out + (r0 + 8) * DD + d) = make_float2(O[nt][2] * i1, O[nt][3] * i1);
    }
}

// ---------------------------------------------------------------------------
extern "C" void kernel_launch(void* const* d_in, const int* in_sizes, int n_in,
                              void* d_out, int out_size)
{
    const float* x    = (const float*)d_in[0];
    const float* w_in = (const float*)d_in[1];
    const float* off  = (const float*)d_in[2];
    const float* amp  = (const float*)d_in[3];
    const float* shp  = (const float*)d_in[4];
    float* out = (float*)d_out;

    // converts + scores in one launch (scores ride as 128 tail blocks)
    convert2_kernel<<<MTOT + D3 + HH * 8, 256>>>(x, w_in, off, amp, shp);

    {
        const int smem_bytes = 3 * STG_BYTES;  // 98304
        cudaFuncSetAttribute(proj_mma, cudaFuncAttributeMaxDynamicSharedMemorySize,
                             smem_bytes);
        dim3 grid(D3 / 128, MTOT / 128);
        proj_mma<<<grid, 256, smem_bytes>>>();
    }

    {
        const int smem_bytes = 49152 + 2 * 192 * 4;  // 50688
        cudaFuncSetAttribute(attn_mma, cudaFuncAttributeMaxDynamicSharedMemorySize,
                             smem_bytes);
        dim3 agrid(LL / 128, HH, BB);
        attn_mma<<<agrid, 256, smem_bytes>>>(out);
    }
}